// round 7
// baseline (speedup 1.0000x reference)
#include <cuda_runtime.h>
#include <cuda_bf16.h>
#include <cstdint>
#include <math.h>

#define N 8192
#define D 128
#define NCTA 296
#define NTT 4160               /* sum over 128 strips of (sj>>1)+1 */
#define NTHR 256
#define C_LOG2 20.60992915555662f   /* (1/0.07) * log2(e) */
#define LN2 0.69314718055994531f
#define THRESH 0.1f

// Scratch (no cudaMalloc allowed)
__device__ __nv_bfloat16 g_fbf[N * D];   // normalized features, bf16, row-major
__device__ float g_den[N];
__device__ float g_ps[N];                // in log2 units (xLN2 at finalize)
__device__ float g_pc[N];
__device__ unsigned int g_done;

// ---- SMEM layout (bytes), per CTA total 83200 ----
#define SM_RES   0          /* resident 64-row j-strip, 16 KB, XOR-swizzled */
#define SM_STR   16384      /* 2 x 32 KB double-buffered streaming A tiles */
#define SM_LABI  81920      /* 2 x 512B double-buffered row labels */
#define SM_LABJ  82944      /* 256B column labels (per strip) */
#define SM_TOTAL 83200

__device__ __forceinline__ uint32_t smem_u32(const void* p) {
    uint32_t a;
    asm("{ .reg .u64 t; cvta.to.shared.u64 t, %1; cvt.u32.u64 %0, t; }" : "=r"(a) : "l"(p));
    return a;
}
__device__ __forceinline__ float ex2(float x) {
    float r;
    asm("ex2.approx.ftz.f32 %0, %1;" : "=f"(r) : "f"(x));
    return r;
}

#define LDSM_X4(r0, r1, r2, r3, addr) \
    asm volatile("ldmatrix.sync.aligned.m8n8.x4.shared.b16 {%0,%1,%2,%3}, [%4];" \
                 : "=r"(r0), "=r"(r1), "=r"(r2), "=r"(r3) : "r"(addr))

#define MMA16816(d, a, b) \
    asm volatile("mma.sync.aligned.m16n8k16.row.col.f32.bf16.bf16.f32 " \
                 "{%0,%1,%2,%3}, {%4,%5,%6,%7}, {%8,%9}, {%0,%1,%2,%3};" \
                 : "+f"((d)[0]), "+f"((d)[1]), "+f"((d)[2]), "+f"((d)[3]) \
                 : "r"((a)[0]), "r"((a)[1]), "r"((a)[2]), "r"((a)[3]), \
                   "r"((b)[0]), "r"((b)[1]))

#define CP_ASYNC16(dst, src) \
    asm volatile("cp.async.cg.shared.global [%0], [%1], 16;" \
                 :: "r"(dst), "l"(src) : "memory")
#define CP_COMMIT() asm volatile("cp.async.commit_group;" ::: "memory")
#define CP_WAIT0()  asm volatile("cp.async.wait_group 0;" ::: "memory")

// swizzled byte offset of (row, 16B-segment) in rows of 256B
__device__ __forceinline__ uint32_t swz(int row, int seg) {
    return (uint32_t)(row * 256 + ((seg ^ (row & 7)) << 4));
}

// cp.async a 128-row A tile (rows rowBase..+127 of g_fbf) into smem
__device__ __forceinline__ void cp_tileA(uint32_t dst_base, int rowBase, int tid) {
    size_t gsrc = __cvta_generic_to_global(g_fbf) + (size_t)rowBase * 256;
    #pragma unroll
    for (int it = 0; it < 8; it++) {
        int u = it * NTHR + tid;         // 2048 16B units
        int row = u >> 4, seg = u & 15;
        CP_ASYNC16(dst_base + swz(row, seg), (const void*)(gsrc + (size_t)u * 16));
    }
}

// cp.async a 64-row strip (rows rowBase..+63) into smem
__device__ __forceinline__ void cp_strip(uint32_t dst_base, int rowBase, int tid) {
    size_t gsrc = __cvta_generic_to_global(g_fbf) + (size_t)rowBase * 256;
    #pragma unroll
    for (int it = 0; it < 4; it++) {
        int u = it * NTHR + tid;         // 1024 16B units
        int row = u >> 4, seg = u & 15;
        CP_ASYNC16(dst_base + swz(row, seg), (const void*)(gsrc + (size_t)u * 16));
    }
}

// ---------------------------------------------------------------------------
// Kernel 1: normalize rows (clamp at 1e-8), quantize to bf16, zero accumulators
// ---------------------------------------------------------------------------
__global__ void prep_kernel(const float* __restrict__ features) {
    int warp = threadIdx.x >> 5, lane = threadIdx.x & 31;
    int row = blockIdx.x * 8 + warp;

    float4 v = ((const float4*)(features + row * D))[lane];
    float ss = v.x * v.x + v.y * v.y + v.z * v.z + v.w * v.w;
    #pragma unroll
    for (int off = 16; off; off >>= 1) ss += __shfl_xor_sync(0xffffffffu, ss, off);
    float sc = 1.0f / fmaxf(sqrtf(ss), 1e-8f);

    __nv_bfloat162 p0 = __floats2bfloat162_rn(v.x * sc, v.y * sc);
    __nv_bfloat162 p1 = __floats2bfloat162_rn(v.z * sc, v.w * sc);
    uint2 st;
    st.x = *(const uint32_t*)&p0;
    st.y = *(const uint32_t*)&p1;
    ((uint2*)(g_fbf + (size_t)row * D))[lane] = st;

    int gt = blockIdx.x * blockDim.x + threadIdx.x;
    if (gt < N) { g_den[gt] = 0.0f; g_ps[gt] = 0.0f; g_pc[gt] = 0.0f; }
    if (gt == 0) g_done = 0;
}

// ---------------------------------------------------------------------------
// Kernel 2: persistent fused HMMA GEMM over 128x64 tiles, column-major
// triangle walk over 128 strips of width 64. 256 threads (8 warps, 4x2 grid,
// 32x32 warp tiles), 2 CTAs co-resident per SM for cross-CTA pipe overlap.
// Diagonal tiles (ti == sj>>1) process only i<j cells with dual update.
// ---------------------------------------------------------------------------
__global__ void __launch_bounds__(NTHR, 2)
main_kernel(const float* __restrict__ labels, float* __restrict__ out) {
    extern __shared__ char smem[];
    const uint32_t sb = smem_u32(smem);
    const int tid  = threadIdx.x;
    const int wid  = tid >> 5;
    const int lane = tid & 31;
    const int wm = wid & 3;          // 0..3 -> m-block of 32
    const int wn = wid >> 2;         // 0..1 -> n-block of 32
    const int quad = lane >> 2;
    const int qt   = lane & 3;

    // --- ldmatrix per-lane bases ---
    const int rowA = wm * 32 + (lane & 15);
    const int hiA  = lane >> 4;
    const int r7A  = rowA & 7;
    const uint32_t aRowOff = (uint32_t)(rowA * 256);
    const int g   = lane >> 3;
    const int r8  = lane & 7;
    const int nrowb = wn * 32 + ((g >> 1) << 3) + r8;  // + p*16 later
    const int segbLo = g & 1;
    const uint32_t bBase = sb + SM_RES + (uint32_t)(nrowb * 256);

    const int t0 = ((int)blockIdx.x * NTT) / NCTA;
    const int t1 = (((int)blockIdx.x + 1) * NTT) / NCTA;

    // map t0 -> (sj, ti): strip sj has (sj>>1)+1 tiles
    int sj = 0, rem = t0;
    while (rem >= (sj >> 1) + 1) { rem -= (sj >> 1) + 1; sj++; }
    int ti = rem;

    // prologue: resident strip(sj) + column labels + first A(ti) + row labels
    cp_strip(sb + SM_RES, sj * 64, tid);
    cp_tileA(sb + SM_STR + (t0 & 1) * 32768, ti * 128, tid);
    {
        size_t lj_src = __cvta_generic_to_global(labels) + (size_t)sj * 256;
        size_t li_src = __cvta_generic_to_global(labels) + (size_t)ti * 512;
        if (tid < 16) CP_ASYNC16(sb + SM_LABJ + tid * 16, (const void*)(lj_src + tid * 16));
        else if (tid < 48)
            CP_ASYNC16(sb + SM_LABI + (t0 & 1) * 512 + (tid - 16) * 16,
                       (const void*)(li_src + (tid - 16) * 16));
    }
    CP_COMMIT();
    CP_WAIT0();
    __syncthreads();

    // column labels for my 8 (ni,c) pairs
    float lj[8];
    #pragma unroll
    for (int p = 0; p < 8; p++)
        lj[p] = ((const float*)(smem + SM_LABJ))[wn * 32 + (p >> 1) * 8 + qt * 2 + (p & 1)];

    // column partials (in registers across the strip)
    float cdn[8], cps[8], cpc[8];
    #pragma unroll
    for (int p = 0; p < 8; p++) { cdn[p] = 0.0f; cps[p] = 0.0f; cpc[p] = 0.0f; }

    for (int t = t0; t < t1; t++) {
        const int s = t & 1;
        const bool have_next = (t + 1) < t1;

        int nti = ti + 1, nsj = sj;
        if (nti > (sj >> 1)) { nsj = sj + 1; nti = 0; }
        const bool strip_change = have_next && (nsj != sj);

        // prefetch A(t+1) + row labels(t+1)
        if (have_next) {
            cp_tileA(sb + SM_STR + ((t + 1) & 1) * 32768, nti * 128, tid);
            if (tid < 32) {
                size_t lsrc = __cvta_generic_to_global(labels) + (size_t)nti * 512;
                CP_ASYNC16(sb + SM_LABI + ((t + 1) & 1) * 512 + tid * 16,
                           (const void*)(lsrc + tid * 16));
            }
            CP_COMMIT();
        }

        // ---- mainloop: 128x64 tile, K=128, warp tile 32x32 ----
        float acc[2][4][4];
        #pragma unroll
        for (int mi = 0; mi < 2; mi++)
            #pragma unroll
            for (int ni = 0; ni < 4; ni++)
                #pragma unroll
                for (int r = 0; r < 4; r++) acc[mi][ni][r] = 0.0f;

        const uint32_t aBase = sb + SM_STR + s * 32768 + aRowOff;
        #pragma unroll
        for (int k = 0; k < 8; k++) {
            uint32_t a[2][4];
            #pragma unroll
            for (int mi = 0; mi < 2; mi++) {
                uint32_t addr = aBase + mi * 4096 + ((((k * 2 + hiA) ^ r7A)) << 4);
                LDSM_X4(a[mi][0], a[mi][1], a[mi][2], a[mi][3], addr);
            }
            uint32_t b[4][2];
            #pragma unroll
            for (int p = 0; p < 2; p++) {
                uint32_t addr = bBase + p * 4096 + ((((k * 2 + segbLo) ^ r8)) << 4);
                LDSM_X4(b[2 * p][0], b[2 * p][1], b[2 * p + 1][0], b[2 * p + 1][1], addr);
            }
            #pragma unroll
            for (int mi = 0; mi < 2; mi++)
                #pragma unroll
                for (int ni = 0; ni < 4; ni++)
                    MMA16816(acc[mi][ni], a[mi], b[ni]);
        }

        // row labels for my 4 m-slots
        const float* slabI = (const float*)(smem + SM_LABI + s * 512);
        float li[4];
        #pragma unroll
        for (int s2 = 0; s2 < 4; s2++)
            li[s2] = slabI[wm * 32 + (s2 >> 1) * 16 + quad + (s2 & 1) * 8];

        // ---- fused epilogue (u = sim * log2e/T; exp(sim) = ex2(u)) ----
        float dn[4] = {0, 0, 0, 0}, ps[4] = {0, 0, 0, 0}, pc[4] = {0, 0, 0, 0};
        const int ibase = ti * 128;
        if (ti == (sj >> 1)) {
            // diagonal tile: only cells with gi < gj count; dual update
            #pragma unroll
            for (int p = 0; p < 8; p++) {
                const int ni = p >> 1, c = p & 1;
                const int gj = sj * 64 + wn * 32 + ni * 8 + qt * 2 + c;
                const float ljp = lj[p];
                float a0 = 0.0f, a1 = 0.0f, a2 = 0.0f;
                #pragma unroll
                for (int mi = 0; mi < 2; mi++) {
                    #pragma unroll
                    for (int rh = 0; rh < 2; rh++) {
                        const int slot = mi * 2 + rh;
                        const int gi = ibase + wm * 32 + mi * 16 + quad + rh * 8;
                        float u = acc[mi][ni][rh * 2 + c] * C_LOG2;
                        bool incl = gi < gj;
                        float e = incl ? ex2(u) : 0.0f;
                        dn[slot] += e;
                        a0 += e;
                        bool pos = incl && (fabsf(li[slot] - ljp) < THRESH);
                        float up = pos ? u : 0.0f;
                        float op = pos ? 1.0f : 0.0f;
                        ps[slot] += up;  a1 += up;
                        pc[slot] += op;  a2 += op;
                    }
                }
                cdn[p] += a0; cps[p] += a1; cpc[p] += a2;
            }
        } else {
            // off-diagonal tile: all cells, dual update
            #pragma unroll
            for (int p = 0; p < 8; p++) {
                const int ni = p >> 1, c = p & 1;
                const float ljp = lj[p];
                float a0 = 0.0f, a1 = 0.0f, a2 = 0.0f;
                #pragma unroll
                for (int mi = 0; mi < 2; mi++) {
                    #pragma unroll
                    for (int rh = 0; rh < 2; rh++) {
                        const int slot = mi * 2 + rh;
                        float u = acc[mi][ni][rh * 2 + c] * C_LOG2;
                        float e = ex2(u);
                        dn[slot] += e;
                        a0 += e;
                        bool pos = fabsf(li[slot] - ljp) < THRESH;
                        float up = pos ? u : 0.0f;
                        float op = pos ? 1.0f : 0.0f;
                        ps[slot] += up;  a1 += up;
                        pc[slot] += op;  a2 += op;
                    }
                }
                cdn[p] += a0; cps[p] += a1; cpc[p] += a2;
            }
        }

        // ---- row flush: every tile. 2-round shuffle over qt lanes.
        #pragma unroll
        for (int s2 = 0; s2 < 4; s2++) {
            float a = dn[s2], b = ps[s2], c = pc[s2];
            a += __shfl_xor_sync(0xffffffffu, a, 1);
            a += __shfl_xor_sync(0xffffffffu, a, 2);
            b += __shfl_xor_sync(0xffffffffu, b, 1);
            b += __shfl_xor_sync(0xffffffffu, b, 2);
            c += __shfl_xor_sync(0xffffffffu, c, 1);
            c += __shfl_xor_sync(0xffffffffu, c, 2);
            if (qt == 0) {
                int gim = ibase + wm * 32 + (s2 >> 1) * 16 + quad + (s2 & 1) * 8;
                atomicAdd(&g_den[gim], a);
                atomicAdd(&g_ps[gim],  b);
                atomicAdd(&g_pc[gim],  c);
            }
        }

        // ---- column flush at strip end / range end (3-round shuffle) ----
        if (strip_change || !have_next) {
            #pragma unroll
            for (int p = 0; p < 8; p++) {
                float a = cdn[p], b = cps[p], c = cpc[p];
                #pragma unroll
                for (int off = 4; off <= 16; off <<= 1) {
                    a += __shfl_xor_sync(0xffffffffu, a, off);
                    b += __shfl_xor_sync(0xffffffffu, b, off);
                    c += __shfl_xor_sync(0xffffffffu, c, off);
                }
                if (quad == 0) {
                    int gj = sj * 64 + wn * 32 + (p >> 1) * 8 + qt * 2 + (p & 1);
                    atomicAdd(&g_den[gj], a);
                    atomicAdd(&g_ps[gj],  b);
                    atomicAdd(&g_pc[gj],  c);
                }
                cdn[p] = 0.0f; cps[p] = 0.0f; cpc[p] = 0.0f;
            }
        }

        CP_WAIT0();            // A(t+1)/labels(t+1) landed
        __syncthreads();       // visible to all; RES/LABJ readers done

        if (strip_change) {
            cp_strip(sb + SM_RES, nsj * 64, tid);
            if (tid < 16) {
                size_t lsrc = __cvta_generic_to_global(labels) + (size_t)nsj * 256;
                CP_ASYNC16(sb + SM_LABJ + tid * 16, (const void*)(lsrc + tid * 16));
            }
            CP_COMMIT();
            CP_WAIT0();
            __syncthreads();
            #pragma unroll
            for (int p = 0; p < 8; p++)
                lj[p] = ((const float*)(smem + SM_LABJ))[wn * 32 + (p >> 1) * 8 + qt * 2 + (p & 1)];
        }
        ti = nti; sj = nsj;
    }

    // ---- last CTA computes the final loss (threadfence + counter pattern) ----
    __threadfence();
    __syncthreads();
    __shared__ unsigned int s_ticket;
    if (tid == 0) s_ticket = atomicAdd(&g_done, 1u);
    __syncthreads();
    if (s_ticket == NCTA - 1) {
        __threadfence();
        float* red = (float*)smem;
        float local = 0.0f;
        for (int i = tid; i < N; i += NTHR)
            local += g_ps[i] / g_pc[i] - log2f(g_den[i]);
        red[tid] = local;
        __syncthreads();
        #pragma unroll
        for (int sft = NTHR / 2; sft; sft >>= 1) {
            if (tid < sft) red[tid] += red[tid + sft];
            __syncthreads();
        }
        if (tid == 0) out[0] = -(LN2 * red[0]) / (float)N;
    }
}

// ---------------------------------------------------------------------------
extern "C" void kernel_launch(void* const* d_in, const int* in_sizes, int n_in,
                              void* d_out, int out_size) {
    const float* features = (const float*)d_in[0];
    const float* labels   = (const float*)d_in[1];
    float* out = (float*)d_out;

    cudaFuncSetAttribute(main_kernel, cudaFuncAttributeMaxDynamicSharedMemorySize, SM_TOTAL);

    prep_kernel<<<N / 8, 256>>>(features);
    main_kernel<<<NCTA, NTHR, SM_TOTAL>>>(labels, out);
}